// round 5
// baseline (speedup 1.0000x reference)
#include <cuda_runtime.h>
#include <math.h>

#define BB 16
#define GG 2048
#define CC 128
#define KK 16
#define TM 64
#define QW 8
#define SCAP 512
#define MLP_T 256

__device__ int g_knn[BB * GG * KK];

// ---------------------------------------------------------------------------
__device__ __forceinline__ unsigned okey(unsigned u) {
    unsigned m = ((unsigned)(((int)u) >> 31)) | 0x80000000u;
    return u ^ m;
}
__device__ __forceinline__ float2 unpack2(unsigned long long v) {
    unsigned lo, hi;
    asm("mov.b64 {%0, %1}, %2;" : "=r"(lo), "=r"(hi) : "l"(v));
    return make_float2(__uint_as_float(lo), __uint_as_float(hi));
}
#define FMA2(acc, a, b) \
    asm("fma.rn.f32x2 %0, %1, %2, %0;" : "+l"(acc) : "l"(a), "l"(b))

// ---------------------------------------------------------------------------
// KNN: warp/query. Float-space threshold filter, 2-way ILP,
// 64KB smem -> 3 blocks/SM. Exact select on survivors.
// ---------------------------------------------------------------------------
__global__ __launch_bounds__(256) void knn_kernel(const float* __restrict__ xyz) {
    extern __shared__ unsigned char ksm[];
    float4* pts = (float4*)ksm;                                      // 32KB
    unsigned long long* svAll = (unsigned long long*)(ksm + GG * 16); // 32KB

    const int tid = threadIdx.x;
    const int b = blockIdx.y;
    const float* p = xyz + (size_t)b * GG * 3;
    for (int i = tid; i < GG; i += 256) {
        float x = p[i * 3 + 0], y = p[i * 3 + 1], z = p[i * 3 + 2];
        pts[i] = make_float4(x, y, z, x * x + y * y + z * z);
    }
    __syncthreads();

    const int w = tid >> 5, lane = tid & 31;
    const unsigned FULL = 0xffffffffu;
    const unsigned lmask = (1u << lane) - 1u;
    unsigned long long* sv = svAll + w * SCAP;

    const int q = blockIdx.x * QW + w;
    const float4 qp = pts[q];
    const float qx = qp.x, qy = qp.y, qz = qp.z;
    // d' = s - 2*dot  (d2 shifted by -qs: order-preserving per query)

    // ---- phase A: 256-sample, binary search 16th key -> tau ----
    unsigned skey[8]; unsigned lmax = 0;
#pragma unroll
    for (int j = 0; j < 8; ++j) {
        int c = (j * 32 + lane) * 8;
        float4 pc = pts[c];
        float t = fmaf(qx, pc.x, fmaf(qy, pc.y, qz * pc.z));
        float d = fmaf(-2.f, t, pc.w);
        skey[j] = okey(__float_as_uint(d));
        lmax = max(lmax, skey[j]);
    }
    unsigned lo = 0, hi = __reduce_max_sync(FULL, lmax);  // count(<=hi)=256>=16
#pragma unroll
    for (int step = 0; step < 18; ++step) {
        unsigned mid = lo + ((hi - lo) >> 1);
        unsigned c = 0;
#pragma unroll
        for (int j = 0; j < 8; ++j) c += (skey[j] <= mid) ? 1u : 0u;
        c = __reduce_add_sync(FULL, c);
        if (c >= KK) hi = mid; else lo = mid + 1;
    }
    // invariant: count_sample(key<=hi) >= 16, so hi >= sample16th >= true16th.
    // inverse okey; NaN-gap values act as +inf plateau
    unsigned fb = (hi & 0x80000000u) ? (hi ^ 0x80000000u) : ~hi;
    float tauf = __uint_as_float(fb);
    if (!(tauf == tauf)) tauf = __uint_as_float(0x7f800000u);

    // ---- phase B: filter + compact survivors (2 candidates per lane/iter) ----
    unsigned scnt = 0;
    for (int j = 0; j < GG / 64; ++j) {
        const int c0 = j * 64 + lane, c1 = c0 + 32;
        const float4 p0 = pts[c0], p1 = pts[c1];
        float t0 = fmaf(qx, p0.x, fmaf(qy, p0.y, qz * p0.z));
        float t1 = fmaf(qx, p1.x, fmaf(qy, p1.y, qz * p1.z));
        float d0 = fmaf(-2.f, t0, p0.w);
        float d1 = fmaf(-2.f, t1, p1.w);
        bool s0 = (d0 <= tauf), s1 = (d1 <= tauf);
        unsigned m0 = __ballot_sync(FULL, s0);
        unsigned m1 = __ballot_sync(FULL, s1);
        unsigned pos0 = scnt + __popc(m0 & lmask);
        unsigned b1c  = scnt + __popc(m0);
        unsigned pos1 = b1c + __popc(m1 & lmask);
        if (s0 && pos0 < SCAP)
            sv[pos0] = ((unsigned long long)__float_as_uint(d0) << 32) | (unsigned)c0;
        if (s1 && pos1 < SCAP)
            sv[pos1] = ((unsigned long long)__float_as_uint(d1) << 32) | (unsigned)c1;
        scnt = b1c + __popc(m1);
    }
    if (scnt > SCAP) scnt = SCAP;
    unsigned padded = (scnt + 31u) & ~31u;
    for (unsigned i = scnt + lane; i < padded; i += 32) sv[i] = ~0ULL;
    __syncwarp();

    // convert float bits -> ordered keys IN SURVIVORS ONLY (padding must stay
    // ~0ULL = max key; converting it would alias to key 0 = min key!)
    const int niter = padded >> 5;
    for (int i = 0; i < niter; ++i) {
        unsigned e = i * 32 + lane;
        if (e < scnt) {
            unsigned long long pk = sv[e];
            unsigned kb = okey((unsigned)(pk >> 32));
            sv[e] = ((unsigned long long)kb << 32) | (unsigned)pk;
        }
    }
    __syncwarp();

    // ---- phase C: exact 16-smallest via 5-bit ballot radix ----
    unsigned need = KK;
    unsigned long long prefix = 0;
    int s = 60;
    bool first = true;
    for (;;) {
        unsigned cntl = 0;
        for (int i = 0; i < niter; ++i) {
            unsigned long long pk = sv[i * 32 + lane];
            bool ok = first || ((pk >> (s + 5)) == prefix);
            unsigned d = (unsigned)(pk >> s) & 31u;
            unsigned mok = __ballot_sync(FULL, ok);
            unsigned m0 = __ballot_sync(FULL, ok && (d & 1u));
            unsigned m1 = __ballot_sync(FULL, ok && (d & 2u));
            unsigned m2 = __ballot_sync(FULL, ok && (d & 4u));
            unsigned m3 = __ballot_sync(FULL, ok && (d & 8u));
            unsigned m4 = __ballot_sync(FULL, ok && (d & 16u));
            unsigned sel = mok;
            sel &= (lane & 1)  ? m0 : ~m0;
            sel &= (lane & 2)  ? m1 : ~m1;
            sel &= (lane & 4)  ? m2 : ~m2;
            sel &= (lane & 8)  ? m3 : ~m3;
            sel &= (lane & 16) ? m4 : ~m4;
            cntl += __popc(sel);
        }
        unsigned run = cntl;
#pragma unroll
        for (int off = 1; off < 32; off <<= 1) {
            unsigned n = __shfl_up_sync(FULL, run, off);
            if (lane >= off) run += n;
        }
        unsigned excl = run - cntl;
        bool has = (excl < need) && (run >= need);
        unsigned hm = __ballot_sync(FULL, has);
        int src = __ffs(hm) - 1;
        unsigned base = __shfl_sync(FULL, excl, src);
        unsigned cnt  = __shfl_sync(FULL, cntl, src);
        prefix = (prefix << 5) | (unsigned)src;
        need -= base;
        first = false;
        if (need == cnt || s == 0) break;
        s -= 5;
    }

    unsigned outc = 0;
    int* outp = g_knn + ((size_t)b * GG + q) * KK;
    for (int i = 0; i < niter && outc < KK; ++i) {
        unsigned long long pk = sv[i * 32 + lane];
        bool sel = (pk >> s) <= prefix;
        unsigned m = __ballot_sync(FULL, sel);
        unsigned pos = outc + __popc(m & lmask);
        if (sel && pos < KK) outp[pos] = (int)(unsigned)pk;
        outc += __popc(m);
    }
}

// ---------------------------------------------------------------------------
// MLP: K-paired f32x2. W pre-interleaved in smem as (W[2c][j],W[2c+1][j])
// pairs -> both GEMM operands are pure LDS.128, zero dup-MOVs.
// 256 thr, TM=64, 4x8 micro-tile, 2 blocks/SM.
// ---------------------------------------------------------------------------
#define MLP_SMEM (TM * CC * 4 + CC * CC * 4 + 2 * CC * 4 + TM * KK * 4)

__device__ __forceinline__ void stage_wp(const float* __restrict__ W,
                                         float* __restrict__ Wp, int tid) {
    // Wp (as ull): Wp[c2*128 + j] = (W[2c2][j], W[2c2+1][j])
    for (int idx = tid; idx < CC * CC / 8; idx += MLP_T) {
        int c2 = idx >> 5, jq = idx & 31;
        float4 a = *(const float4*)(W + (2 * c2) * CC + jq * 4);
        float4 b = *(const float4*)(W + (2 * c2 + 1) * CC + jq * 4);
        float* dst = Wp + c2 * (2 * CC) + jq * 8;
        *(float4*)(dst + 0) = make_float4(a.x, b.x, a.y, b.y);
        *(float4*)(dst + 4) = make_float4(a.z, b.z, a.w, b.w);
    }
}

__device__ __forceinline__ void gemm_kpair(const float* __restrict__ As,
                                           const float* __restrict__ Wp,
                                           int r0, int j0, float (&res)[4][8]) {
    unsigned long long acc[4][8];
#pragma unroll
    for (int i = 0; i < 4; ++i)
#pragma unroll
        for (int j = 0; j < 8; ++j) acc[i][j] = 0ULL;

    const unsigned long long* Wu = (const unsigned long long*)Wp;
    for (int c2 = 0; c2 < CC / 2; c2 += 2) {
        ulonglong2 av[4];
#pragma unroll
        for (int i = 0; i < 4; ++i)
            av[i] = *(const ulonglong2*)(As + (r0 + i) * CC + c2 * 2);
        {
            const ulonglong2* wp = (const ulonglong2*)(Wu + (size_t)c2 * CC + j0);
            ulonglong2 wa = wp[0], wb = wp[1], wc = wp[2], wd = wp[3];
            unsigned long long wv[8] = {wa.x, wa.y, wb.x, wb.y, wc.x, wc.y, wd.x, wd.y};
#pragma unroll
            for (int i = 0; i < 4; ++i)
#pragma unroll
                for (int j = 0; j < 8; ++j)
                    FMA2(acc[i][j], av[i].x, wv[j]);
        }
        {
            const ulonglong2* wp = (const ulonglong2*)(Wu + (size_t)(c2 + 1) * CC + j0);
            ulonglong2 wa = wp[0], wb = wp[1], wc = wp[2], wd = wp[3];
            unsigned long long wv[8] = {wa.x, wa.y, wb.x, wb.y, wc.x, wc.y, wd.x, wd.y};
#pragma unroll
            for (int i = 0; i < 4; ++i)
#pragma unroll
                for (int j = 0; j < 8; ++j)
                    FMA2(acc[i][j], av[i].y, wv[j]);
        }
    }
#pragma unroll
    for (int i = 0; i < 4; ++i)
#pragma unroll
        for (int j = 0; j < 8; ++j) {
            float2 v = unpack2(acc[i][j]);
            res[i][j] = v.x + v.y;
        }
}

__global__ __launch_bounds__(MLP_T, 2) void mlp_kernel(const float* __restrict__ feat,
                                                       const float* __restrict__ W1,
                                                       const float* __restrict__ b1,
                                                       const float* __restrict__ W2,
                                                       const float* __restrict__ b2,
                                                       float* __restrict__ out) {
    extern __shared__ __align__(16) float sm[];
    float* As   = sm;                  // TM * CC row-major
    float* Wp   = As + TM * CC;        // CC*CC floats, K-pair interleaved
    float* bs   = Wp + CC * CC;        // 2 * CC
    int*   sidx = (int*)(bs + 2 * CC); // TM * KK

    const int tid = threadIdx.x;
    const int rowBase = blockIdx.x * TM;
    const int b = rowBase >> 11;
    const float* fb = feat + (size_t)b * GG * CC;

    for (int i = tid; i < TM * KK; i += MLP_T) sidx[i] = g_knn[(size_t)rowBase * KK + i];
    stage_wp(W1, Wp, tid);
    if (tid < CC) { bs[tid] = b1[tid]; bs[CC + tid] = b2[tid]; }
    __syncthreads();

    // gather + L2 pool -> As row-major
    {
        const int lane = tid & 31, warp = tid >> 5;
        for (int pass = 0; pass < TM / 8; ++pass) {
            const int r = pass * 8 + warp;
            const int* ip = sidx + r * KK;
            float4 acc = make_float4(0.f, 0.f, 0.f, 0.f);
#pragma unroll
            for (int k = 0; k < KK; ++k) {
                const float4 f = *reinterpret_cast<const float4*>(
                    fb + (size_t)ip[k] * CC + lane * 4);
                acc.x = fmaf(f.x, f.x, acc.x);
                acc.y = fmaf(f.y, f.y, acc.y);
                acc.z = fmaf(f.z, f.z, acc.z);
                acc.w = fmaf(f.w, f.w, acc.w);
            }
            acc.x = sqrtf(acc.x); acc.y = sqrtf(acc.y);
            acc.z = sqrtf(acc.z); acc.w = sqrtf(acc.w);
            *reinterpret_cast<float4*>(As + r * CC + lane * 4) = acc;
        }
    }
    __syncthreads();

    const int ty = tid >> 4, tx = tid & 15;
    const int r0 = ty * 4, j0 = tx * 8;

    float h[4][8];
    gemm_kpair(As, Wp, r0, j0, h);

#pragma unroll
    for (int i = 0; i < 4; ++i)
#pragma unroll
        for (int j = 0; j < 8; ++j) {
            float v = h[i][j] + bs[j0 + j];
            h[i][j] = 0.5f * v * (1.f + erff(v * 0.70710678118654752f));
        }
    __syncthreads();   // GEMM1 smem reads done

    // H -> As, W2 -> Wp
#pragma unroll
    for (int i = 0; i < 4; ++i) {
        float* hp = As + (r0 + i) * CC + j0;
        *(float4*)(hp)     = make_float4(h[i][0], h[i][1], h[i][2], h[i][3]);
        *(float4*)(hp + 4) = make_float4(h[i][4], h[i][5], h[i][6], h[i][7]);
    }
    stage_wp(W2, Wp, tid);
    __syncthreads();

    float o[4][8];
    gemm_kpair(As, Wp, r0, j0, o);

#pragma unroll
    for (int i = 0; i < 4; ++i) {
        float* op = out + (size_t)(rowBase + r0 + i) * CC + j0;
        *(float4*)(op)     = make_float4(o[i][0] + bs[CC + j0 + 0],
                                         o[i][1] + bs[CC + j0 + 1],
                                         o[i][2] + bs[CC + j0 + 2],
                                         o[i][3] + bs[CC + j0 + 3]);
        *(float4*)(op + 4) = make_float4(o[i][4] + bs[CC + j0 + 4],
                                         o[i][5] + bs[CC + j0 + 5],
                                         o[i][6] + bs[CC + j0 + 6],
                                         o[i][7] + bs[CC + j0 + 7]);
    }
}

// ---------------------------------------------------------------------------
extern "C" void kernel_launch(void* const* d_in, const int* in_sizes, int n_in,
                              void* d_out, int out_size) {
    const float* xyz  = (const float*)d_in[0];
    const float* feat = (const float*)d_in[1];
    const float* W1   = (const float*)d_in[2];
    const float* b1   = (const float*)d_in[3];
    const float* W2   = (const float*)d_in[4];
    const float* b2   = (const float*)d_in[5];
    float* out = (float*)d_out;

    const int KNN_SMEM = GG * 16 + QW * SCAP * 8;   // 64 KB -> 3 blocks/SM
    cudaFuncSetAttribute(knn_kernel, cudaFuncAttributeMaxDynamicSharedMemorySize,
                         KNN_SMEM);
    dim3 gknn(GG / QW, BB);
    knn_kernel<<<gknn, 256, KNN_SMEM>>>(xyz);

    cudaFuncSetAttribute(mlp_kernel, cudaFuncAttributeMaxDynamicSharedMemorySize,
                         MLP_SMEM);
    mlp_kernel<<<(BB * GG) / TM, MLP_T, MLP_SMEM>>>(feat, W1, b1, W2, b2, out);
}